// round 1
// baseline (speedup 1.0000x reference)
#include <cuda_runtime.h>
#include <cuda_bf16.h>
#include <math.h>

// Problem constants (fixed shapes)
#define T_TOK   4096          // B*S = 2*2048
#define H_DIM   1024
#define I_DIM   1408
#define E_NUM   8
#define TOPK    2
#define N_ASG   (T_TOK * TOPK)   // 8192

// Scratch (device globals — no allocations allowed)
__device__ float d_h[N_ASG * I_DIM];       // silu(g)*u per assignment  (~46 MB)
__device__ float d_yslot[N_ASG * H_DIM];   // per-(token,slot) expert output (~33.5 MB)
__device__ int   d_asg[E_NUM * T_TOK];     // per-expert assignment lists (values = t*2+slot)
__device__ float d_topw[N_ASG];            // combine weight per assignment
__device__ int   d_topi[N_ASG];            // expert id per assignment
__device__ int   d_count[E_NUM];           // tokens per expert

// ---------------------------------------------------------------------------
// 1) Router: logits -> softmax -> top2. One block per token, warp e -> expert e.
// ---------------------------------------------------------------------------
__global__ void router_kernel(const float* __restrict__ x,
                              const float* __restrict__ rw)
{
    int t = blockIdx.x;
    int w = threadIdx.x >> 5;
    int lane = threadIdx.x & 31;

    const float* xr = x + (size_t)t * H_DIM;
    const float* wr = rw + (size_t)w * H_DIM;

    float acc = 0.f;
    #pragma unroll 4
    for (int k = lane; k < H_DIM; k += 32)
        acc += xr[k] * wr[k];
    #pragma unroll
    for (int o = 16; o > 0; o >>= 1)
        acc += __shfl_xor_sync(0xffffffffu, acc, o);

    __shared__ float logits[E_NUM];
    if (lane == 0) logits[w] = acc;
    __syncthreads();

    if (threadIdx.x == 0) {
        float mx = logits[0];
        #pragma unroll
        for (int e = 1; e < E_NUM; e++) mx = fmaxf(mx, logits[e]);
        float ex[E_NUM]; float s = 0.f;
        #pragma unroll
        for (int e = 0; e < E_NUM; e++) { ex[e] = expf(logits[e] - mx); s += ex[e]; }
        float inv = 1.f / s;

        // top-1 (strict > keeps lowest index on ties, matching top_k)
        int i0 = 0;
        #pragma unroll
        for (int e = 1; e < E_NUM; e++) if (ex[e] > ex[i0]) i0 = e;
        // top-2
        int i1 = (i0 == 0) ? 1 : 0;
        #pragma unroll
        for (int e = 0; e < E_NUM; e++)
            if (e != i0 && ex[e] > ex[i1]) i1 = e;

        d_topi[t * 2 + 0] = i0;  d_topw[t * 2 + 0] = ex[i0] * inv;
        d_topi[t * 2 + 1] = i1;  d_topw[t * 2 + 1] = ex[i1] * inv;
    }
}

// ---------------------------------------------------------------------------
// 2) Deterministic per-expert list build. 1 block, warp e compacts expert e
//    in assignment order (no atomics -> deterministic).
// ---------------------------------------------------------------------------
__global__ void build_lists_kernel()
{
    int w = threadIdx.x >> 5;
    int lane = threadIdx.x & 31;
    unsigned lt = (1u << lane) - 1u;
    int base = 0;
    for (int s = 0; s < N_ASG; s += 32) {
        int idx = s + lane;
        int e = d_topi[idx];
        bool p = (e == w);
        unsigned m = __ballot_sync(0xffffffffu, p);
        if (p) d_asg[w * T_TOK + base + __popc(m & lt)] = idx;
        base += __popc(m);
    }
    if (lane == 0) d_count[w] = base;
}

// ---------------------------------------------------------------------------
// 3) GEMM1: per expert, gathered-A GEMM producing gate & up columns together,
//    fused SiLU(g)*u epilogue into d_h.
//    Tiles: BM=64 (rows=assignments), BN=64 (cols over I), BK=32.
// ---------------------------------------------------------------------------
#define BM 64
#define BN 64
#define BK 32

__global__ __launch_bounds__(256)
void gemm1_kernel(const float* __restrict__ x,
                  const float* __restrict__ gup)
{
    int e = blockIdx.z;
    int cnt = d_count[e];
    int row0 = blockIdx.y * BM;
    if (row0 >= cnt) return;
    int col0 = blockIdx.x * BN;           // over I (22*64 = 1408 exact)

    __shared__ float As[BK][BM + 1];
    __shared__ float Bg[BK][BN + 1];
    __shared__ float Bu[BK][BN + 1];
    __shared__ int   toks[BM];

    int tid = threadIdx.x;
    if (tid < BM) {
        int r = row0 + tid;
        toks[tid] = (r < cnt) ? d_asg[e * T_TOK + r] : -1;
    }
    __syncthreads();

    const float* W = gup + (size_t)e * (2 * I_DIM) * H_DIM;

    float accg[4][4] = {};
    float accu[4][4] = {};

    int lr = tid >> 5;     // 0..7
    int lk = tid & 31;     // 0..31 (= k within tile)
    int ty = tid >> 4;     // 0..15
    int tx = tid & 15;     // 0..15
    int mt = ty << 2;
    int nt = tx << 2;

    for (int k0 = 0; k0 < H_DIM; k0 += BK) {
        #pragma unroll
        for (int m = lr; m < BM; m += 8) {
            int a = toks[m];
            float v = 0.f;
            if (a >= 0) v = x[(size_t)(a >> 1) * H_DIM + k0 + lk];
            As[lk][m] = v;
        }
        #pragma unroll
        for (int n = lr; n < BN; n += 8) {
            int o = col0 + n;
            Bg[lk][n] = W[(size_t)o * H_DIM + k0 + lk];
            Bu[lk][n] = W[(size_t)(o + I_DIM) * H_DIM + k0 + lk];
        }
        __syncthreads();

        #pragma unroll
        for (int k = 0; k < BK; k++) {
            float af[4], bgf[4], buf_[4];
            #pragma unroll
            for (int i = 0; i < 4; i++) af[i]  = As[k][mt + i];
            #pragma unroll
            for (int j = 0; j < 4; j++) bgf[j] = Bg[k][nt + j];
            #pragma unroll
            for (int j = 0; j < 4; j++) buf_[j] = Bu[k][nt + j];
            #pragma unroll
            for (int i = 0; i < 4; i++)
                #pragma unroll
                for (int j = 0; j < 4; j++) {
                    accg[i][j] = fmaf(af[i], bgf[j], accg[i][j]);
                    accu[i][j] = fmaf(af[i], buf_[j], accu[i][j]);
                }
        }
        __syncthreads();
    }

    #pragma unroll
    for (int i = 0; i < 4; i++) {
        int r = row0 + mt + i;
        if (r < cnt) {
            int a = toks[mt + i];
            size_t base = (size_t)a * I_DIM + col0 + nt;
            #pragma unroll
            for (int j = 0; j < 4; j++) {
                float g = accg[i][j];
                float u = accu[i][j];
                float sg = g / (1.f + expf(-g));   // silu
                d_h[base + j] = sg * u;
            }
        }
    }
}

// ---------------------------------------------------------------------------
// 4) GEMM2: y[a, hcol] = sum_i h[a,i] * down[e][hcol,i], scaled by weight.
// ---------------------------------------------------------------------------
__global__ __launch_bounds__(256)
void gemm2_kernel(const float* __restrict__ down)
{
    int e = blockIdx.z;
    int cnt = d_count[e];
    int row0 = blockIdx.y * BM;
    if (row0 >= cnt) return;
    int col0 = blockIdx.x * BN;           // over H (16*64 = 1024 exact)

    __shared__ float As[BK][BM + 1];
    __shared__ float Bs[BK][BN + 1];
    __shared__ int   toks[BM];

    int tid = threadIdx.x;
    if (tid < BM) {
        int r = row0 + tid;
        toks[tid] = (r < cnt) ? d_asg[e * T_TOK + r] : -1;
    }
    __syncthreads();

    const float* D = down + (size_t)e * H_DIM * I_DIM;

    float acc[4][4] = {};

    int lr = tid >> 5;
    int lk = tid & 31;
    int ty = tid >> 4;
    int tx = tid & 15;
    int mt = ty << 2;
    int nt = tx << 2;

    for (int k0 = 0; k0 < I_DIM; k0 += BK) {
        #pragma unroll
        for (int m = lr; m < BM; m += 8) {
            int a = toks[m];
            float v = 0.f;
            if (a >= 0) v = d_h[(size_t)a * I_DIM + k0 + lk];
            As[lk][m] = v;
        }
        #pragma unroll
        for (int n = lr; n < BN; n += 8) {
            int hc = col0 + n;
            Bs[lk][n] = D[(size_t)hc * I_DIM + k0 + lk];
        }
        __syncthreads();

        #pragma unroll
        for (int k = 0; k < BK; k++) {
            float af[4], bf[4];
            #pragma unroll
            for (int i = 0; i < 4; i++) af[i] = As[k][mt + i];
            #pragma unroll
            for (int j = 0; j < 4; j++) bf[j] = Bs[k][nt + j];
            #pragma unroll
            for (int i = 0; i < 4; i++)
                #pragma unroll
                for (int j = 0; j < 4; j++)
                    acc[i][j] = fmaf(af[i], bf[j], acc[i][j]);
        }
        __syncthreads();
    }

    #pragma unroll
    for (int i = 0; i < 4; i++) {
        int r = row0 + mt + i;
        if (r < cnt) {
            int a = toks[mt + i];
            float wgt = d_topw[a];
            size_t base = (size_t)a * H_DIM + col0 + nt;
            #pragma unroll
            for (int j = 0; j < 4; j++)
                d_yslot[base + j] = acc[i][j] * wgt;
        }
    }
}

// ---------------------------------------------------------------------------
// 5) Combine: out[t,h] = yslot[t*2,h] + yslot[t*2+1,h]  (float4 vectorized)
// ---------------------------------------------------------------------------
__global__ void combine_kernel(float* __restrict__ out)
{
    int i = blockIdx.x * blockDim.x + threadIdx.x;      // over T*H/4 float4s
    int t  = i >> 8;                                     // 1024/4 = 256 f4/token
    int h4 = i & 255;
    const float4* y4 = reinterpret_cast<const float4*>(d_yslot);
    float4 a = y4[(size_t)t * 512 + h4];
    float4 b = y4[(size_t)t * 512 + 256 + h4];
    float4 r;
    r.x = a.x + b.x; r.y = a.y + b.y; r.z = a.z + b.z; r.w = a.w + b.w;
    reinterpret_cast<float4*>(out)[i] = r;
}

// ---------------------------------------------------------------------------
extern "C" void kernel_launch(void* const* d_in, const int* in_sizes, int n_in,
                              void* d_out, int out_size)
{
    const float* hidden = (const float*)d_in[0];  // [2,2048,1024]
    const float* rw     = (const float*)d_in[1];  // [8,1024]
    const float* gup    = (const float*)d_in[2];  // [8,2816,1024]
    const float* down   = (const float*)d_in[3];  // [8,1024,1408]
    float* out          = (float*)d_out;          // [2,2048,1024]

    // 1) router
    router_kernel<<<T_TOK, 256>>>(hidden, rw);

    // 2) deterministic per-expert lists
    build_lists_kernel<<<1, 256>>>();

    // 3) GEMM1 + fused SiLU*up
    {
        dim3 grid(I_DIM / BN, T_TOK / BM, E_NUM);   // 22 x 64 x 8
        gemm1_kernel<<<grid, 256>>>(hidden, gup);
    }

    // 4) GEMM2 (+weight scale)
    {
        dim3 grid(H_DIM / BN, T_TOK / BM, E_NUM);   // 16 x 64 x 8
        gemm2_kernel<<<grid, 256>>>(down);
    }

    // 5) combine slots
    {
        int n4 = T_TOK * H_DIM / 4;
        combine_kernel<<<n4 / 256, 256>>>(out);
    }
}

// round 3
// speedup vs baseline: 2.7930x; 2.7930x over previous
#include <cuda_runtime.h>
#include <cuda_bf16.h>
#include <math.h>
#include <cstdint>

// ===========================================================================
// Problem constants
// ===========================================================================
#define T_TOK   4096
#define H_DIM   1024
#define I_DIM   1408
#define E_NUM   8
#define N_ASG   (T_TOK * 2)

// Tiling
#define BM      128
#define BN      128
#define BK      32                 // fp32 K per slab
#define KB      96                 // bf16 cols per slab (3 split segments)
#define STRIDE  104                // padded bf16 cols
#define SBYTES  (STRIDE * 2)       // 208 B row stride (13*16 -> 16B aligned)
#define TILEB   (BM * SBYTES)      // 26624 B per tile
#define SMEM_BYTES (4 * TILEB)     // A0,B0,A1,B1 = 106496 B

// Scratch
__device__ float d_h[N_ASG * I_DIM];
__device__ float d_yslot[N_ASG * H_DIM];
__device__ int   d_asg[E_NUM * T_TOK];
__device__ float d_topw[N_ASG];
__device__ int   d_topi[N_ASG];
__device__ int   d_count[E_NUM];

// ===========================================================================
// Helpers
// ===========================================================================
__device__ __forceinline__ uint32_t smem_u32(const void* p) {
    uint32_t a;
    asm("{ .reg .u64 t; cvta.to.shared.u64 t, %1; cvt.u32.u64 %0, t; }" : "=r"(a) : "l"(p));
    return a;
}
__device__ __forceinline__ void ldsm_x4(uint32_t& r0, uint32_t& r1, uint32_t& r2, uint32_t& r3,
                                        uint32_t addr) {
    asm volatile("ldmatrix.sync.aligned.m8n8.x4.shared.b16 {%0,%1,%2,%3}, [%4];"
        : "=r"(r0), "=r"(r1), "=r"(r2), "=r"(r3) : "r"(addr));
}
__device__ __forceinline__ void mma_bf16(float* c, uint32_t a0, uint32_t a1, uint32_t a2,
                                         uint32_t a3, uint32_t b0, uint32_t b1) {
    asm volatile("mma.sync.aligned.m16n8k16.row.col.f32.bf16.bf16.f32 "
        "{%0,%1,%2,%3}, {%4,%5,%6,%7}, {%8,%9}, {%0,%1,%2,%3};"
        : "+f"(c[0]), "+f"(c[1]), "+f"(c[2]), "+f"(c[3])
        : "r"(a0), "r"(a1), "r"(a2), "r"(a3), "r"(b0), "r"(b1));
}
// fp32 pair -> bf16x2 hi + bf16x2 lo
__device__ __forceinline__ void split2(float x, float y, uint32_t& hi, uint32_t& lo) {
    __nv_bfloat162 h2 = __float22bfloat162_rn(make_float2(x, y));
    float2 hf = __bfloat1622float2(h2);
    __nv_bfloat162 l2 = __float22bfloat162_rn(make_float2(x - hf.x, y - hf.y));
    hi = *reinterpret_cast<uint32_t*>(&h2);
    lo = *reinterpret_cast<uint32_t*>(&l2);
}
// A layout: hi at cols [c], dup hi at [c+32], lo at [c+64]
__device__ __forceinline__ void store_a4(char* row, int c, float4 v) {
    uint32_t h0, l0, h1, l1;
    split2(v.x, v.y, h0, l0);
    split2(v.z, v.w, h1, l1);
    char* p = row + c * 2;
    *reinterpret_cast<uint2*>(p)       = make_uint2(h0, h1);
    *reinterpret_cast<uint2*>(p + 64)  = make_uint2(h0, h1);
    *reinterpret_cast<uint2*>(p + 128) = make_uint2(l0, l1);
}
// B layout: hi at [c], lo at [c+32], dup hi at [c+64]
__device__ __forceinline__ void store_b4(char* row, int c, float4 v) {
    uint32_t h0, l0, h1, l1;
    split2(v.x, v.y, h0, l0);
    split2(v.z, v.w, h1, l1);
    char* p = row + c * 2;
    *reinterpret_cast<uint2*>(p)       = make_uint2(h0, h1);
    *reinterpret_cast<uint2*>(p + 64)  = make_uint2(l0, l1);
    *reinterpret_cast<uint2*>(p + 128) = make_uint2(h0, h1);
}

// ===========================================================================
// 1) Router
// ===========================================================================
__global__ void router_kernel(const float* __restrict__ x, const float* __restrict__ rw)
{
    int t = blockIdx.x;
    int w = threadIdx.x >> 5;
    int lane = threadIdx.x & 31;
    const float* xr = x + (size_t)t * H_DIM;
    const float* wr = rw + (size_t)w * H_DIM;
    float acc = 0.f;
    #pragma unroll 4
    for (int k = lane; k < H_DIM; k += 32) acc += xr[k] * wr[k];
    #pragma unroll
    for (int o = 16; o > 0; o >>= 1) acc += __shfl_xor_sync(0xffffffffu, acc, o);
    __shared__ float logits[E_NUM];
    if (lane == 0) logits[w] = acc;
    __syncthreads();
    if (threadIdx.x == 0) {
        float mx = logits[0];
        #pragma unroll
        for (int e = 1; e < E_NUM; e++) mx = fmaxf(mx, logits[e]);
        float ex[E_NUM]; float s = 0.f;
        #pragma unroll
        for (int e = 0; e < E_NUM; e++) { ex[e] = expf(logits[e] - mx); s += ex[e]; }
        float inv = 1.f / s;
        int i0 = 0;
        #pragma unroll
        for (int e = 1; e < E_NUM; e++) if (ex[e] > ex[i0]) i0 = e;
        int i1 = (i0 == 0) ? 1 : 0;
        #pragma unroll
        for (int e = 0; e < E_NUM; e++) if (e != i0 && ex[e] > ex[i1]) i1 = e;
        d_topi[t * 2 + 0] = i0;  d_topw[t * 2 + 0] = ex[i0] * inv;
        d_topi[t * 2 + 1] = i1;  d_topw[t * 2 + 1] = ex[i1] * inv;
    }
}

// ===========================================================================
// 2) Deterministic per-expert lists
// ===========================================================================
__global__ void build_lists_kernel()
{
    int w = threadIdx.x >> 5;
    int lane = threadIdx.x & 31;
    unsigned lt = (1u << lane) - 1u;
    int base = 0;
    for (int s = 0; s < N_ASG; s += 32) {
        int idx = s + lane;
        int e = d_topi[idx];
        bool p = (e == w);
        unsigned m = __ballot_sync(0xffffffffu, p);
        if (p) d_asg[w * T_TOK + base + __popc(m & lt)] = idx;
        base += __popc(m);
    }
    if (lane == 0) d_count[w] = base;
}

// ===========================================================================
// 3) GEMM1: h = silu(x Wg^T) * (x Wu^T), bf16-split HMMA
//    B tile rows: 8-col groups alternate gate/up for the same h columns.
// ===========================================================================
__global__ __launch_bounds__(256, 1)
void gemm1_tc(const float* __restrict__ x, const float* __restrict__ gup)
{
    int e = blockIdx.z;
    int cnt = d_count[e];
    int row0 = blockIdx.y * BM;
    if (row0 >= cnt) return;
    int col0 = blockIdx.x * 64;                 // h columns per CTA

    extern __shared__ char sm[];
    __shared__ int toks[BM];
    int tid = threadIdx.x, lane = tid & 31, wid = tid >> 5;

    if (tid < BM) {
        int r = row0 + tid;
        toks[tid] = (r < cnt) ? d_asg[e * T_TOK + r] : -1;
    }
    __syncthreads();

    // loader: thread -> (row, half)
    int lr = tid >> 1, lh = tid & 1;
    int atok = toks[lr];
    const float* aptr = (atok >= 0) ? x + (size_t)(atok >> 1) * H_DIM + lh * 16 : nullptr;
    int g = lr >> 3, pr = g >> 1, sub = g & 1;
    int o = col0 + pr * 8 + (lr & 7) + (sub ? I_DIM : 0);
    const float* bptr = gup + (size_t)e * (2 * I_DIM) * H_DIM + (size_t)o * H_DIM + lh * 16;

    // compute: warp (wm, wn)
    int wm = wid >> 2, wn = wid & 3;
    uint32_t sbase = smem_u32(sm);
    uint32_t aoff = (uint32_t)(wm * 64 + (lane & 15)) * SBYTES + (lane >> 4) * 16;
    uint32_t boff = (uint32_t)(wn * 32 + (lane & 7) + ((lane >> 4) & 1) * 8) * SBYTES
                  + ((lane >> 3) & 1) * 16;

    float c[4][4][4] = {};
    float4 av[4], bv[4];
    #pragma unroll
    for (int j = 0; j < 4; j++) {
        av[j] = aptr ? reinterpret_cast<const float4*>(aptr)[j * 1 + 0 * 0] : make_float4(0,0,0,0);
    }
    // (re-load with proper addressing below; keep simple explicit prefetch)
    #pragma unroll
    for (int j = 0; j < 4; j++) {
        av[j] = aptr ? *reinterpret_cast<const float4*>(aptr + j * 4) : make_float4(0,0,0,0);
        bv[j] = *reinterpret_cast<const float4*>(bptr + j * 4);
    }

    const int NK = H_DIM / BK;   // 32
    #pragma unroll 2
    for (int i = 0; i < NK; i++) {
        int b = i & 1;
        char* A = sm + b * 2 * TILEB;
        char* B = A + TILEB;
        char* arow = A + lr * SBYTES;
        char* brow = B + lr * SBYTES;
        #pragma unroll
        for (int j = 0; j < 4; j++) {
            int cc = lh * 16 + j * 4;
            store_a4(arow, cc, av[j]);
            store_b4(brow, cc, bv[j]);
        }
        __syncthreads();
        if (i + 1 < NK) {
            int k0 = (i + 1) * BK;
            #pragma unroll
            for (int j = 0; j < 4; j++) {
                av[j] = aptr ? *reinterpret_cast<const float4*>(aptr + k0 + j * 4)
                             : make_float4(0,0,0,0);
                bv[j] = *reinterpret_cast<const float4*>(bptr + k0 + j * 4);
            }
        }
        uint32_t sA = sbase + b * 2 * TILEB + aoff;
        uint32_t sB = sbase + b * 2 * TILEB + TILEB + boff;
        #pragma unroll
        for (int ks = 0; ks < 6; ks++) {
            uint32_t a0[4], a1[4], a2[4], a3[4];
            uint32_t bb[4][2];
            #pragma unroll
            for (int mf = 0; mf < 4; mf++)
                ldsm_x4(a0[mf], a1[mf], a2[mf], a3[mf], sA + mf * 16 * SBYTES + ks * 32);
            #pragma unroll
            for (int np = 0; np < 2; np++) {
                uint32_t b0, b1, b2, b3;
                ldsm_x4(b0, b1, b2, b3, sB + np * 16 * SBYTES + ks * 32);
                bb[np * 2][0] = b0; bb[np * 2][1] = b1;
                bb[np * 2 + 1][0] = b2; bb[np * 2 + 1][1] = b3;
            }
            #pragma unroll
            for (int mf = 0; mf < 4; mf++)
                #pragma unroll
                for (int nf = 0; nf < 4; nf++)
                    mma_bf16(c[mf][nf], a0[mf], a1[mf], a2[mf], a3[mf], bb[nf][0], bb[nf][1]);
        }
    }

    // Epilogue: fuse silu(gate)*up; gate = nf even, up = nf odd, same (row,col)
    int tg = lane >> 2, ti = lane & 3;
    #pragma unroll
    for (int mf = 0; mf < 4; mf++) {
        #pragma unroll
        for (int q2 = 0; q2 < 2; q2++) {
            int rloc = wm * 64 + mf * 16 + tg + q2 * 8;
            int a = toks[rloc];
            if (a < 0) continue;
            float* dst = d_h + (size_t)a * I_DIM;
            #pragma unroll
            for (int p = 0; p < 2; p++) {
                int hc = col0 + (wn * 2 + p) * 8 + ti * 2;
                float g0 = c[mf][2 * p][q2 * 2 + 0], u0 = c[mf][2 * p + 1][q2 * 2 + 0];
                float g1 = c[mf][2 * p][q2 * 2 + 1], u1 = c[mf][2 * p + 1][q2 * 2 + 1];
                dst[hc]     = u0 * (g0 / (1.f + __expf(-g0)));
                dst[hc + 1] = u1 * (g1 / (1.f + __expf(-g1)));
            }
        }
    }
}

// ===========================================================================
// 4) GEMM2: y = (h down^T) * weight
// ===========================================================================
__global__ __launch_bounds__(256, 1)
void gemm2_tc(const float* __restrict__ down)
{
    int e = blockIdx.z;
    int cnt = d_count[e];
    int row0 = blockIdx.y * BM;
    if (row0 >= cnt) return;
    int col0 = blockIdx.x * BN;                 // H columns per CTA

    extern __shared__ char sm[];
    __shared__ int toks[BM];
    int tid = threadIdx.x, lane = tid & 31, wid = tid >> 5;

    if (tid < BM) {
        int r = row0 + tid;
        toks[tid] = (r < cnt) ? d_asg[e * T_TOK + r] : -1;
    }
    __syncthreads();

    int lr = tid >> 1, lh = tid & 1;
    int atok = toks[lr];
    const float* aptr = (atok >= 0) ? d_h + (size_t)atok * I_DIM + lh * 16 : nullptr;
    const float* bptr = down + (size_t)e * H_DIM * I_DIM + (size_t)(col0 + lr) * I_DIM + lh * 16;

    int wm = wid >> 2, wn = wid & 3;
    uint32_t sbase = smem_u32(sm);
    uint32_t aoff = (uint32_t)(wm * 64 + (lane & 15)) * SBYTES + (lane >> 4) * 16;
    uint32_t boff = (uint32_t)(wn * 32 + (lane & 7) + ((lane >> 4) & 1) * 8) * SBYTES
                  + ((lane >> 3) & 1) * 16;

    float c[4][4][4] = {};
    float4 av[4], bv[4];
    #pragma unroll
    for (int j = 0; j < 4; j++) {
        av[j] = aptr ? *reinterpret_cast<const float4*>(aptr + j * 4) : make_float4(0,0,0,0);
        bv[j] = *reinterpret_cast<const float4*>(bptr + j * 4);
    }

    const int NK = I_DIM / BK;   // 44
    #pragma unroll 2
    for (int i = 0; i < NK; i++) {
        int b = i & 1;
        char* A = sm + b * 2 * TILEB;
        char* B = A + TILEB;
        char* arow = A + lr * SBYTES;
        char* brow = B + lr * SBYTES;
        #pragma unroll
        for (int j = 0; j < 4; j++) {
            int cc = lh * 16 + j * 4;
            store_a4(arow, cc, av[j]);
            store_b4(brow, cc, bv[j]);
        }
        __syncthreads();
        if (i + 1 < NK) {
            int k0 = (i + 1) * BK;
            #pragma unroll
            for (int j = 0; j < 4; j++) {
                av[j] = aptr ? *reinterpret_cast<const float4*>(aptr + k0 + j * 4)
                             : make_float4(0,0,0,0);
                bv[j] = *reinterpret_cast<const float4*>(bptr + k0 + j * 4);
            }
        }
        uint32_t sA = sbase + b * 2 * TILEB + aoff;
        uint32_t sB = sbase + b * 2 * TILEB + TILEB + boff;
        #pragma unroll
        for (int ks = 0; ks < 6; ks++) {
            uint32_t a0[4], a1[4], a2[4], a3[4];
            uint32_t bb[4][2];
            #pragma unroll
            for (int mf = 0; mf < 4; mf++)
                ldsm_x4(a0[mf], a1[mf], a2[mf], a3[mf], sA + mf * 16 * SBYTES + ks * 32);
            #pragma unroll
            for (int np = 0; np < 2; np++) {
                uint32_t b0, b1, b2, b3;
                ldsm_x4(b0, b1, b2, b3, sB + np * 16 * SBYTES + ks * 32);
                bb[np * 2][0] = b0; bb[np * 2][1] = b1;
                bb[np * 2 + 1][0] = b2; bb[np * 2 + 1][1] = b3;
            }
            #pragma unroll
            for (int mf = 0; mf < 4; mf++)
                #pragma unroll
                for (int nf = 0; nf < 4; nf++)
                    mma_bf16(c[mf][nf], a0[mf], a1[mf], a2[mf], a3[mf], bb[nf][0], bb[nf][1]);
        }
    }

    int tg = lane >> 2, ti = lane & 3;
    #pragma unroll
    for (int mf = 0; mf < 4; mf++) {
        #pragma unroll
        for (int q2 = 0; q2 < 2; q2++) {
            int rloc = wm * 64 + mf * 16 + tg + q2 * 8;
            int a = toks[rloc];
            if (a < 0) continue;
            float wgt = d_topw[a];
            float* dst = d_yslot + (size_t)a * H_DIM;
            #pragma unroll
            for (int nf = 0; nf < 4; nf++) {
                int colc = col0 + wn * 32 + nf * 8 + ti * 2;
                dst[colc]     = c[mf][nf][q2 * 2 + 0] * wgt;
                dst[colc + 1] = c[mf][nf][q2 * 2 + 1] * wgt;
            }
        }
    }
}

// ===========================================================================
// 5) Combine
// ===========================================================================
__global__ void combine_kernel(float* __restrict__ out)
{
    int i = blockIdx.x * blockDim.x + threadIdx.x;
    int t = i >> 8;
    int h4 = i & 255;
    const float4* y4 = reinterpret_cast<const float4*>(d_yslot);
    float4 a = y4[(size_t)t * 512 + h4];
    float4 b = y4[(size_t)t * 512 + 256 + h4];
    float4 rr;
    rr.x = a.x + b.x; rr.y = a.y + b.y; rr.z = a.z + b.z; rr.w = a.w + b.w;
    reinterpret_cast<float4*>(out)[i] = rr;
}

// ===========================================================================
extern "C" void kernel_launch(void* const* d_in, const int* in_sizes, int n_in,
                              void* d_out, int out_size)
{
    const float* hidden = (const float*)d_in[0];
    const float* rw     = (const float*)d_in[1];
    const float* gup    = (const float*)d_in[2];
    const float* down   = (const float*)d_in[3];
    float* out          = (float*)d_out;

    static bool attr_done = false;
    if (!attr_done) {
        cudaFuncSetAttribute(gemm1_tc, cudaFuncAttributeMaxDynamicSharedMemorySize, SMEM_BYTES);
        cudaFuncSetAttribute(gemm2_tc, cudaFuncAttributeMaxDynamicSharedMemorySize, SMEM_BYTES);
        attr_done = true;
    }

    router_kernel<<<T_TOK, 256>>>(hidden, rw);
    build_lists_kernel<<<1, 256>>>();

    {
        dim3 grid(I_DIM / 64, T_TOK / BM, E_NUM);    // 22 x 32 x 8
        gemm1_tc<<<grid, 256, SMEM_BYTES>>>(hidden, gup);
    }
    {
        dim3 grid(H_DIM / BN, T_TOK / BM, E_NUM);    // 8 x 32 x 8
        gemm2_tc<<<grid, 256, SMEM_BYTES>>>(down);
    }
    {
        int n4 = T_TOK * H_DIM / 4;
        combine_kernel<<<n4 / 256, 256>>>(out);
    }
}

// round 4
// speedup vs baseline: 3.0700x; 1.0992x over previous
#include <cuda_runtime.h>
#include <cuda_bf16.h>
#include <math.h>
#include <cstdint>

// ===========================================================================
// Problem constants
// ===========================================================================
#define T_TOK   4096
#define H_DIM   1024
#define I_DIM   1408
#define E_NUM   8
#define N_ASG   (T_TOK * 2)

// Tiling: CTA 128x128, 8 warps = 2(m) x 2(n) x 2(k-split), warp tile 64x64
#define BM      128
#define BN      128
#define SBY     144                 // row stride bytes (9*16 -> odd 16B multiple)
#define TILEB   (128 * SBY)         // 18432 B per operand tile
#define STAGEB  (2 * TILEB)         // A + B per buffer = 36864
#define SMEM_BYTES (2 * STAGEB)     // double buffered = 73728
#define RST     66                  // reduction row stride (floats)

// Scratch
__device__ float d_h[N_ASG * I_DIM];
__device__ float d_yslot[N_ASG * H_DIM];
__device__ int   d_asg[E_NUM * T_TOK];
__device__ float d_topw[N_ASG];
__device__ int   d_topi[N_ASG];
__device__ int   d_count[E_NUM];

// ===========================================================================
// Helpers
// ===========================================================================
__device__ __forceinline__ uint32_t smem_u32(const void* p) {
    uint32_t a;
    asm("{ .reg .u64 t; cvta.to.shared.u64 t, %1; cvt.u32.u64 %0, t; }" : "=r"(a) : "l"(p));
    return a;
}
__device__ __forceinline__ void ldsm_x4(uint32_t& r0, uint32_t& r1, uint32_t& r2, uint32_t& r3,
                                        uint32_t addr) {
    asm volatile("ldmatrix.sync.aligned.m8n8.x4.shared.b16 {%0,%1,%2,%3}, [%4];"
        : "=r"(r0), "=r"(r1), "=r"(r2), "=r"(r3) : "r"(addr));
}
__device__ __forceinline__ void mma_bf16(float* c, uint32_t a0, uint32_t a1, uint32_t a2,
                                         uint32_t a3, uint32_t b0, uint32_t b1) {
    asm volatile("mma.sync.aligned.m16n8k16.row.col.f32.bf16.bf16.f32 "
        "{%0,%1,%2,%3}, {%4,%5,%6,%7}, {%8,%9}, {%0,%1,%2,%3};"
        : "+f"(c[0]), "+f"(c[1]), "+f"(c[2]), "+f"(c[3])
        : "r"(a0), "r"(a1), "r"(a2), "r"(a3), "r"(b0), "r"(b1));
}
__device__ __forceinline__ void split2(float x, float y, uint32_t& hi, uint32_t& lo) {
    __nv_bfloat162 h2 = __float22bfloat162_rn(make_float2(x, y));
    float2 hf = __bfloat1622float2(h2);
    __nv_bfloat162 l2 = __float22bfloat162_rn(make_float2(x - hf.x, y - hf.y));
    hi = *reinterpret_cast<uint32_t*>(&h2);
    lo = *reinterpret_cast<uint32_t*>(&l2);
}
// Convert 16 fp32 (4 float4) -> hi seg bytes [0,64) + lo seg [64,128) of the row
__device__ __forceinline__ void cvt_store(char* row, int lh, const float4* v) {
    uint32_t h[8], l[8];
    #pragma unroll
    for (int j = 0; j < 4; j++) {
        split2(v[j].x, v[j].y, h[2*j],   l[2*j]);
        split2(v[j].z, v[j].w, h[2*j+1], l[2*j+1]);
    }
    *reinterpret_cast<uint4*>(row + lh*32)          = make_uint4(h[0],h[1],h[2],h[3]);
    *reinterpret_cast<uint4*>(row + lh*32 + 16)     = make_uint4(h[4],h[5],h[6],h[7]);
    *reinterpret_cast<uint4*>(row + 64 + lh*32)     = make_uint4(l[0],l[1],l[2],l[3]);
    *reinterpret_cast<uint4*>(row + 64 + lh*32 + 16)= make_uint4(l[4],l[5],l[6],l[7]);
}

// ===========================================================================
// 1) Router
// ===========================================================================
__global__ void router_kernel(const float* __restrict__ x, const float* __restrict__ rw)
{
    int t = blockIdx.x;
    int w = threadIdx.x >> 5;
    int lane = threadIdx.x & 31;
    const float* xr = x + (size_t)t * H_DIM;
    const float* wr = rw + (size_t)w * H_DIM;
    float acc = 0.f;
    #pragma unroll 4
    for (int k = lane; k < H_DIM; k += 32) acc += xr[k] * wr[k];
    #pragma unroll
    for (int o = 16; o > 0; o >>= 1) acc += __shfl_xor_sync(0xffffffffu, acc, o);
    __shared__ float logits[E_NUM];
    if (lane == 0) logits[w] = acc;
    __syncthreads();
    if (threadIdx.x == 0) {
        float mx = logits[0];
        #pragma unroll
        for (int e = 1; e < E_NUM; e++) mx = fmaxf(mx, logits[e]);
        float ex[E_NUM]; float s = 0.f;
        #pragma unroll
        for (int e = 0; e < E_NUM; e++) { ex[e] = expf(logits[e] - mx); s += ex[e]; }
        float inv = 1.f / s;
        int i0 = 0;
        #pragma unroll
        for (int e = 1; e < E_NUM; e++) if (ex[e] > ex[i0]) i0 = e;
        int i1 = (i0 == 0) ? 1 : 0;
        #pragma unroll
        for (int e = 0; e < E_NUM; e++) if (e != i0 && ex[e] > ex[i1]) i1 = e;
        d_topi[t * 2 + 0] = i0;  d_topw[t * 2 + 0] = ex[i0] * inv;
        d_topi[t * 2 + 1] = i1;  d_topw[t * 2 + 1] = ex[i1] * inv;
    }
}

// ===========================================================================
// 2) Deterministic per-expert lists
// ===========================================================================
__global__ void build_lists_kernel()
{
    int w = threadIdx.x >> 5;
    int lane = threadIdx.x & 31;
    unsigned lt = (1u << lane) - 1u;
    int base = 0;
    for (int s = 0; s < N_ASG; s += 32) {
        int idx = s + lane;
        int e = d_topi[idx];
        bool p = (e == w);
        unsigned m = __ballot_sync(0xffffffffu, p);
        if (p) d_asg[w * T_TOK + base + __popc(m & lt)] = idx;
        base += __popc(m);
    }
    if (lane == 0) d_count[w] = base;
}

// ===========================================================================
// Shared GEMM core macro pieces (written inline in each kernel)
//   MMA section per slab/buffer: warp (wk, wm, wn), fragments hi|lo segments.
// ===========================================================================
#define MMA_SLAB(sbaseb)                                                        \
    {                                                                           \
        uint32_t sA = (sbaseb) + aoff;                                          \
        uint32_t sB = (sbaseb) + TILEB + boff;                                  \
        uint32_t ah[4][4], bh[8][2];                                            \
        _Pragma("unroll")                                                       \
        for (int mf = 0; mf < 4; mf++)                                          \
            ldsm_x4(ah[mf][0], ah[mf][1], ah[mf][2], ah[mf][3],                 \
                    sA + mf * 16 * SBY);                                        \
        _Pragma("unroll")                                                       \
        for (int nb = 0; nb < 4; nb++) {                                        \
            uint32_t t0, t1, t2, t3;                                            \
            ldsm_x4(t0, t1, t2, t3, sB + nb * 16 * SBY);                        \
            bh[2*nb][0] = t0; bh[2*nb][1] = t1;                                 \
            bh[2*nb+1][0] = t2; bh[2*nb+1][1] = t3;                             \
        }                                                                       \
        _Pragma("unroll")                                                       \
        for (int mf = 0; mf < 4; mf++)                                          \
            _Pragma("unroll")                                                   \
            for (int nf = 0; nf < 8; nf++)                                      \
                mma_bf16(c[mf][nf], ah[mf][0], ah[mf][1], ah[mf][2], ah[mf][3], \
                         bh[nf][0], bh[nf][1]);                                 \
        {                                                                       \
            uint32_t al[4][4];                                                  \
            _Pragma("unroll")                                                   \
            for (int mf = 0; mf < 4; mf++)                                      \
                ldsm_x4(al[mf][0], al[mf][1], al[mf][2], al[mf][3],             \
                        sA + mf * 16 * SBY + 64);                               \
            _Pragma("unroll")                                                   \
            for (int mf = 0; mf < 4; mf++)                                      \
                _Pragma("unroll")                                               \
                for (int nf = 0; nf < 8; nf++)                                  \
                    mma_bf16(c[mf][nf], al[mf][0], al[mf][1], al[mf][2],        \
                             al[mf][3], bh[nf][0], bh[nf][1]);                  \
        }                                                                       \
        {                                                                       \
            uint32_t bl[8][2];                                                  \
            _Pragma("unroll")                                                   \
            for (int nb = 0; nb < 4; nb++) {                                    \
                uint32_t t0, t1, t2, t3;                                        \
                ldsm_x4(t0, t1, t2, t3, sB + nb * 16 * SBY + 64);               \
                bl[2*nb][0] = t0; bl[2*nb][1] = t1;                             \
                bl[2*nb+1][0] = t2; bl[2*nb+1][1] = t3;                         \
            }                                                                   \
            _Pragma("unroll")                                                   \
            for (int mf = 0; mf < 4; mf++)                                      \
                _Pragma("unroll")                                               \
                for (int nf = 0; nf < 8; nf++)                                  \
                    mma_bf16(c[mf][nf], ah[mf][0], ah[mf][1], ah[mf][2],        \
                             ah[mf][3], bl[nf][0], bl[nf][1]);                  \
        }                                                                       \
    }

// split-K reduction through smem; leaves summed values in wk==0 warps' c
#define KSPLIT_REDUCE()                                                         \
    __syncthreads();                                                            \
    {                                                                           \
        float* red = reinterpret_cast<float*>(sm);                              \
        float* rb = red + (wm * 2 + wn) * 64 * RST;                             \
        if (wk == 1) {                                                          \
            _Pragma("unroll")                                                   \
            for (int mf = 0; mf < 4; mf++)                                      \
                _Pragma("unroll")                                               \
                for (int h = 0; h < 2; h++) {                                   \
                    int row = mf * 16 + tg + 8 * h;                             \
                    float2* rr = reinterpret_cast<float2*>(rb + row * RST);     \
                    _Pragma("unroll")                                           \
                    for (int nf = 0; nf < 8; nf++)                              \
                        rr[nf * 4 + ti] =                                       \
                            make_float2(c[mf][nf][2*h], c[mf][nf][2*h+1]);      \
                }                                                               \
        }                                                                       \
        __syncthreads();                                                        \
        if (wk == 0) {                                                          \
            _Pragma("unroll")                                                   \
            for (int mf = 0; mf < 4; mf++)                                      \
                _Pragma("unroll")                                               \
                for (int h = 0; h < 2; h++) {                                   \
                    int row = mf * 16 + tg + 8 * h;                             \
                    float2* rr = reinterpret_cast<float2*>(rb + row * RST);     \
                    _Pragma("unroll")                                           \
                    for (int nf = 0; nf < 8; nf++) {                            \
                        float2 t = rr[nf * 4 + ti];                             \
                        c[mf][nf][2*h]   += t.x;                                \
                        c[mf][nf][2*h+1] += t.y;                                \
                    }                                                           \
                }                                                               \
        }                                                                       \
    }

// ===========================================================================
// 3) GEMM1: h = silu(x Wg^T) * (x Wu^T)
//    B tile rows: groups of 8 alternate gate/up for the same 8 h-columns.
// ===========================================================================
__global__ __launch_bounds__(256, 1)
void gemm1_tc(const float* __restrict__ x, const float* __restrict__ gup)
{
    int e = blockIdx.z;
    int cnt = d_count[e];
    int row0 = blockIdx.y * BM;
    if (row0 >= cnt) return;
    int col0 = blockIdx.x * 64;                 // h columns per CTA

    extern __shared__ char sm[];
    __shared__ int toks[BM];
    int tid = threadIdx.x, lane = tid & 31, wid = tid >> 5;

    if (tid < BM) {
        int r = row0 + tid;
        toks[tid] = (r < cnt) ? d_asg[e * T_TOK + r] : -1;
    }
    __syncthreads();

    // loader: thread -> (row, k-half of 16 fp32)
    int lr = tid >> 1, lh = tid & 1;
    int atok = toks[lr];
    const float* aptr = (atok >= 0) ? x + (size_t)(atok >> 1) * H_DIM + lh * 16 : nullptr;
    int g = lr >> 3, pr = g >> 1, sub = g & 1;
    int o = col0 + pr * 8 + (lr & 7) + (sub ? I_DIM : 0);
    const float* bptr = gup + (size_t)e * (2 * I_DIM) * H_DIM + (size_t)o * H_DIM + lh * 16;

    // compute warp coords: 2(m) x 2(n) x 2(k-split)
    int wk = wid >> 2, wm = (wid >> 1) & 1, wn = wid & 1;
    int tg = lane >> 2, ti = lane & 3;
    uint32_t sbase = smem_u32(sm);
    uint32_t aoff = (uint32_t)(wm * 64 + (lane & 15)) * SBY + wk * 32 + (lane >> 4) * 16;
    uint32_t boff = (uint32_t)(wn * 64 + (lane & 7) + ((lane >> 4) & 1) * 8) * SBY
                  + wk * 32 + ((lane >> 3) & 1) * 16;

    float c[4][8][4] = {};
    float4 av[4], bv[4];
    #pragma unroll
    for (int j = 0; j < 4; j++) {
        av[j] = aptr ? *reinterpret_cast<const float4*>(aptr + j * 4) : make_float4(0,0,0,0);
        bv[j] = *reinterpret_cast<const float4*>(bptr + j * 4);
    }

    const int NK = H_DIM / 32;   // 32
    for (int i = 0; i < NK; i++) {
        int b = i & 1;
        char* A = sm + b * STAGEB;
        cvt_store(A + lr * SBY, lh, av);
        cvt_store(A + TILEB + lr * SBY, lh, bv);
        __syncthreads();
        if (i + 1 < NK) {
            int k0 = (i + 1) * 32;
            #pragma unroll
            for (int j = 0; j < 4; j++) {
                av[j] = aptr ? *reinterpret_cast<const float4*>(aptr + k0 + j * 4)
                             : make_float4(0,0,0,0);
                bv[j] = *reinterpret_cast<const float4*>(bptr + k0 + j * 4);
            }
        }
        MMA_SLAB(sbase + b * STAGEB);
    }

    KSPLIT_REDUCE();

    // Epilogue (wk==0 warps): fuse silu(gate)*up
    if (wk == 0) {
        #pragma unroll
        for (int mf = 0; mf < 4; mf++) {
            #pragma unroll
            for (int h = 0; h < 2; h++) {
                int rloc = wm * 64 + mf * 16 + tg + 8 * h;
                int a = toks[rloc];
                if (a < 0) continue;
                float* dst = d_h + (size_t)a * I_DIM;
                #pragma unroll
                for (int q = 0; q < 4; q++) {
                    float g0 = c[mf][2*q][2*h],   u0 = c[mf][2*q+1][2*h];
                    float g1 = c[mf][2*q][2*h+1], u1 = c[mf][2*q+1][2*h+1];
                    int hc = col0 + (wn * 4 + q) * 8 + ti * 2;
                    dst[hc]     = u0 * (g0 / (1.f + __expf(-g0)));
                    dst[hc + 1] = u1 * (g1 / (1.f + __expf(-g1)));
                }
            }
        }
    }
}

// ===========================================================================
// 4) GEMM2: y = (h down^T) * weight
// ===========================================================================
__global__ __launch_bounds__(256, 1)
void gemm2_tc(const float* __restrict__ down)
{
    int e = blockIdx.z;
    int cnt = d_count[e];
    int row0 = blockIdx.y * BM;
    if (row0 >= cnt) return;
    int col0 = blockIdx.x * BN;                 // H columns per CTA

    extern __shared__ char sm[];
    __shared__ int toks[BM];
    int tid = threadIdx.x, lane = tid & 31, wid = tid >> 5;

    if (tid < BM) {
        int r = row0 + tid;
        toks[tid] = (r < cnt) ? d_asg[e * T_TOK + r] : -1;
    }
    __syncthreads();

    int lr = tid >> 1, lh = tid & 1;
    int atok = toks[lr];
    const float* aptr = (atok >= 0) ? d_h + (size_t)atok * I_DIM + lh * 16 : nullptr;
    const float* bptr = down + (size_t)e * H_DIM * I_DIM + (size_t)(col0 + lr) * I_DIM + lh * 16;

    int wk = wid >> 2, wm = (wid >> 1) & 1, wn = wid & 1;
    int tg = lane >> 2, ti = lane & 3;
    uint32_t sbase = smem_u32(sm);
    uint32_t aoff = (uint32_t)(wm * 64 + (lane & 15)) * SBY + wk * 32 + (lane >> 4) * 16;
    uint32_t boff = (uint32_t)(wn * 64 + (lane & 7) + ((lane >> 4) & 1) * 8) * SBY
                  + wk * 32 + ((lane >> 3) & 1) * 16;

    float c[4][8][4] = {};
    float4 av[4], bv[4];
    #pragma unroll
    for (int j = 0; j < 4; j++) {
        av[j] = aptr ? *reinterpret_cast<const float4*>(aptr + j * 4) : make_float4(0,0,0,0);
        bv[j] = *reinterpret_cast<const float4*>(bptr + j * 4);
    }

    const int NK = I_DIM / 32;   // 44
    for (int i = 0; i < NK; i++) {
        int b = i & 1;
        char* A = sm + b * STAGEB;
        cvt_store(A + lr * SBY, lh, av);
        cvt_store(A + TILEB + lr * SBY, lh, bv);
        __syncthreads();
        if (i + 1 < NK) {
            int k0 = (i + 1) * 32;
            #pragma unroll
            for (int j = 0; j < 4; j++) {
                av[j] = aptr ? *reinterpret_cast<const float4*>(aptr + k0 + j * 4)
                             : make_float4(0,0,0,0);
                bv[j] = *reinterpret_cast<const float4*>(bptr + k0 + j * 4);
            }
        }
        MMA_SLAB(sbase + b * STAGEB);
    }

    KSPLIT_REDUCE();

    if (wk == 0) {
        #pragma unroll
        for (int mf = 0; mf < 4; mf++) {
            #pragma unroll
            for (int h = 0; h < 2; h++) {
                int rloc = wm * 64 + mf * 16 + tg + 8 * h;
                int a = toks[rloc];
                if (a < 0) continue;
                float wgt = d_topw[a];
                float* dst = d_yslot + (size_t)a * H_DIM;
                #pragma unroll
                for (int nf = 0; nf < 8; nf++) {
                    int colc = col0 + wn * 64 + nf * 8 + ti * 2;
                    dst[colc]     = c[mf][nf][2*h]   * wgt;
                    dst[colc + 1] = c[mf][nf][2*h+1] * wgt;
                }
            }
        }
    }
}

// ===========================================================================
// 5) Combine
// ===========================================================================
__global__ void combine_kernel(float* __restrict__ out)
{
    int i = blockIdx.x * blockDim.x + threadIdx.x;
    int t = i >> 8;
    int h4 = i & 255;
    const float4* y4 = reinterpret_cast<const float4*>(d_yslot);
    float4 a = y4[(size_t)t * 512 + h4];
    float4 b = y4[(size_t)t * 512 + 256 + h4];
    float4 rr;
    rr.x = a.x + b.x; rr.y = a.y + b.y; rr.z = a.z + b.z; rr.w = a.w + b.w;
    reinterpret_cast<float4*>(out)[i] = rr;
}

// ===========================================================================
extern "C" void kernel_launch(void* const* d_in, const int* in_sizes, int n_in,
                              void* d_out, int out_size)
{
    const float* hidden = (const float*)d_in[0];
    const float* rw     = (const float*)d_in[1];
    const float* gup    = (const float*)d_in[2];
    const float* down   = (const float*)d_in[3];
    float* out          = (float*)d_out;

    static bool attr_done = false;
    if (!attr_done) {
        cudaFuncSetAttribute(gemm1_tc, cudaFuncAttributeMaxDynamicSharedMemorySize, SMEM_BYTES);
        cudaFuncSetAttribute(gemm2_tc, cudaFuncAttributeMaxDynamicSharedMemorySize, SMEM_BYTES);
        attr_done = true;
    }

    router_kernel<<<T_TOK, 256>>>(hidden, rw);
    build_lists_kernel<<<1, 256>>>();

    {
        dim3 grid(I_DIM / 64, T_TOK / BM, E_NUM);    // 22 x 32 x 8
        gemm1_tc<<<grid, 256, SMEM_BYTES>>>(hidden, gup);
    }
    {
        dim3 grid(H_DIM / BN, T_TOK / BM, E_NUM);    // 8 x 32 x 8
        gemm2_tc<<<grid, 256, SMEM_BYTES>>>(down);
    }
    {
        int n4 = T_TOK * H_DIM / 4;
        combine_kernel<<<n4 / 256, 256>>>(out);
    }
}

// round 7
// speedup vs baseline: 3.1466x; 1.0250x over previous
#include <cuda_runtime.h>
#include <cuda_bf16.h>
#include <math.h>
#include <cstdint>

// ===========================================================================
// Problem constants
// ===========================================================================
#define T_TOK   4096
#define H_DIM   1024
#define I_DIM   1408
#define E_NUM   8
#define N_ASG   (T_TOK * 2)
#define NKX     32                  // H_DIM/32 slabs
#define NKH     44                  // I_DIM/32 slabs

// Tiling: CTA 128x128, 8 warps = 2(m) x 2(n) x 2(k-split), warp tile 64x64
#define BM      128
#define BN      128
#define SBY     144                 // smem row stride bytes
#define TILEB   (128 * SBY)         // 18432 B per operand tile
#define STAGEB  (2 * TILEB)         // A + B per buffer = 36864
#define SMEM_BYTES (2 * STAGEB)     // double buffered = 73728
#define RST     66                  // reduction row stride (floats)

// Pre-converted gmem: per (row, 32k-slab) one 128B block = [64B hi bf16 | 64B lo bf16]
__device__ __align__(128) unsigned char xbuf[(size_t)T_TOK * NKX * 128];
__device__ __align__(128) unsigned char w1buf[(size_t)E_NUM * 2816 * NKX * 128];
__device__ __align__(128) unsigned char w2buf[(size_t)E_NUM * 1024 * NKH * 128];
__device__ __align__(128) unsigned char hbuf[(size_t)N_ASG * NKH * 128];
__device__ float d_yslot[(size_t)N_ASG * H_DIM];
__device__ int   d_asg[E_NUM * T_TOK];
__device__ float d_topw[N_ASG];
__device__ int   d_topi[N_ASG];
__device__ int   d_count[E_NUM];

// ===========================================================================
// Helpers
// ===========================================================================
__device__ __forceinline__ uint32_t smem_u32(const void* p) {
    uint32_t a;
    asm("{ .reg .u64 t; cvta.to.shared.u64 t, %1; cvt.u32.u64 %0, t; }" : "=r"(a) : "l"(p));
    return a;
}
__device__ __forceinline__ void ldsm_x4(uint32_t& r0, uint32_t& r1, uint32_t& r2, uint32_t& r3,
                                        uint32_t addr) {
    asm volatile("ldmatrix.sync.aligned.m8n8.x4.shared.b16 {%0,%1,%2,%3}, [%4];"
        : "=r"(r0), "=r"(r1), "=r"(r2), "=r"(r3) : "r"(addr));
}
__device__ __forceinline__ void mma_bf16(float* c, uint32_t a0, uint32_t a1, uint32_t a2,
                                         uint32_t a3, uint32_t b0, uint32_t b1) {
    asm volatile("mma.sync.aligned.m16n8k16.row.col.f32.bf16.bf16.f32 "
        "{%0,%1,%2,%3}, {%4,%5,%6,%7}, {%8,%9}, {%0,%1,%2,%3};"
        : "+f"(c[0]), "+f"(c[1]), "+f"(c[2]), "+f"(c[3])
        : "r"(a0), "r"(a1), "r"(a2), "r"(a3), "r"(b0), "r"(b1));
}
__device__ __forceinline__ void split2(float x, float y, uint32_t& hi, uint32_t& lo) {
    __nv_bfloat162 h2 = __float22bfloat162_rn(make_float2(x, y));
    float2 hf = __bfloat1622float2(h2);
    __nv_bfloat162 l2 = __float22bfloat162_rn(make_float2(x - hf.x, y - hf.y));
    hi = *reinterpret_cast<uint32_t*>(&h2);
    lo = *reinterpret_cast<uint32_t*>(&l2);
}

// ===========================================================================
// 0) Pre-convert fp32 -> [64B hi | 64B lo] per (row, 32k-slab)
//    dst selected INSIDE device code (host cannot pass __device__ symbols).
// ===========================================================================
__global__ void conv_hl(const float* __restrict__ src, int which, int total)
{
    int idx = blockIdx.x * 256 + threadIdx.x;
    if (idx >= total) return;
    unsigned char* dst = (which == 0) ? xbuf : (which == 1) ? w1buf : w2buf;
    int p = idx & 3;
    size_t rs = (size_t)(idx >> 2);
    const float4* s = reinterpret_cast<const float4*>(src + rs * 32 + p * 8);
    float4 v0 = s[0], v1 = s[1];
    uint32_t h[4], l[4];
    split2(v0.x, v0.y, h[0], l[0]);
    split2(v0.z, v0.w, h[1], l[1]);
    split2(v1.x, v1.y, h[2], l[2]);
    split2(v1.z, v1.w, h[3], l[3]);
    unsigned char* d = dst + rs * 128 + p * 16;
    *reinterpret_cast<uint4*>(d)      = make_uint4(h[0], h[1], h[2], h[3]);
    *reinterpret_cast<uint4*>(d + 64) = make_uint4(l[0], l[1], l[2], l[3]);
}

// ===========================================================================
// 1) Router
// ===========================================================================
__global__ void router_kernel(const float* __restrict__ x, const float* __restrict__ rw)
{
    int t = blockIdx.x;
    int w = threadIdx.x >> 5;
    int lane = threadIdx.x & 31;
    const float* xr = x + (size_t)t * H_DIM;
    const float* wr = rw + (size_t)w * H_DIM;
    float acc = 0.f;
    #pragma unroll 4
    for (int k = lane; k < H_DIM; k += 32) acc += xr[k] * wr[k];
    #pragma unroll
    for (int o = 16; o > 0; o >>= 1) acc += __shfl_xor_sync(0xffffffffu, acc, o);
    __shared__ float logits[E_NUM];
    if (lane == 0) logits[w] = acc;
    __syncthreads();
    if (threadIdx.x == 0) {
        float mx = logits[0];
        #pragma unroll
        for (int e = 1; e < E_NUM; e++) mx = fmaxf(mx, logits[e]);
        float ex[E_NUM]; float s = 0.f;
        #pragma unroll
        for (int e = 0; e < E_NUM; e++) { ex[e] = expf(logits[e] - mx); s += ex[e]; }
        float inv = 1.f / s;
        int i0 = 0;
        #pragma unroll
        for (int e = 1; e < E_NUM; e++) if (ex[e] > ex[i0]) i0 = e;
        int i1 = (i0 == 0) ? 1 : 0;
        #pragma unroll
        for (int e = 0; e < E_NUM; e++) if (e != i0 && ex[e] > ex[i1]) i1 = e;
        d_topi[t * 2 + 0] = i0;  d_topw[t * 2 + 0] = ex[i0] * inv;
        d_topi[t * 2 + 1] = i1;  d_topw[t * 2 + 1] = ex[i1] * inv;
    }
}

// ===========================================================================
// 2) Deterministic per-expert lists
// ===========================================================================
__global__ void build_lists_kernel()
{
    int w = threadIdx.x >> 5;
    int lane = threadIdx.x & 31;
    unsigned lt = (1u << lane) - 1u;
    int base = 0;
    for (int s = 0; s < N_ASG; s += 32) {
        int idx = s + lane;
        int e = d_topi[idx];
        bool p = (e == w);
        unsigned m = __ballot_sync(0xffffffffu, p);
        if (p) d_asg[w * T_TOK + base + __popc(m & lt)] = idx;
        base += __popc(m);
    }
    if (lane == 0) d_count[w] = base;
}

// ===========================================================================
// Loader: copy one preconverted 128B block half (hi 32B + lo 32B)
// ===========================================================================
__device__ __forceinline__ void load_blk(uint4* v, const unsigned char* src, int lh, bool valid) {
    if (valid) {
        v[0] = *reinterpret_cast<const uint4*>(src + lh * 32);
        v[1] = *reinterpret_cast<const uint4*>(src + lh * 32 + 16);
        v[2] = *reinterpret_cast<const uint4*>(src + 64 + lh * 32);
        v[3] = *reinterpret_cast<const uint4*>(src + 64 + lh * 32 + 16);
    } else {
        v[0] = v[1] = v[2] = v[3] = make_uint4(0, 0, 0, 0);
    }
}
__device__ __forceinline__ void store_blk(char* row, int lh, const uint4* v) {
    *reinterpret_cast<uint4*>(row + lh * 32)          = v[0];
    *reinterpret_cast<uint4*>(row + lh * 32 + 16)     = v[1];
    *reinterpret_cast<uint4*>(row + 64 + lh * 32)     = v[2];
    *reinterpret_cast<uint4*>(row + 64 + lh * 32 + 16)= v[3];
}

// ===========================================================================
// MMA on one slab buffer — Round-4 proven structure (SBY layout, lo at +64)
// ===========================================================================
#define MMA_SLAB(sbaseb)                                                        \
    {                                                                           \
        uint32_t sA = (sbaseb) + aoff;                                          \
        uint32_t sB = (sbaseb) + TILEB + boff;                                  \
        uint32_t ah[4][4], bh[8][2];                                            \
        _Pragma("unroll")                                                       \
        for (int mf = 0; mf < 4; mf++)                                          \
            ldsm_x4(ah[mf][0], ah[mf][1], ah[mf][2], ah[mf][3],                 \
                    sA + mf * 16 * SBY);                                        \
        _Pragma("unroll")                                                       \
        for (int nb = 0; nb < 4; nb++) {                                        \
            uint32_t t0, t1, t2, t3;                                            \
            ldsm_x4(t0, t1, t2, t3, sB + nb * 16 * SBY);                        \
            bh[2*nb][0] = t0; bh[2*nb][1] = t1;                                 \
            bh[2*nb+1][0] = t2; bh[2*nb+1][1] = t3;                             \
        }                                                                       \
        _Pragma("unroll")                                                       \
        for (int mf = 0; mf < 4; mf++)                                          \
            _Pragma("unroll")                                                   \
            for (int nf = 0; nf < 8; nf++)                                      \
                mma_bf16(c[mf][nf], ah[mf][0], ah[mf][1], ah[mf][2], ah[mf][3], \
                         bh[nf][0], bh[nf][1]);                                 \
        {                                                                       \
            uint32_t al[4][4];                                                  \
            _Pragma("unroll")                                                   \
            for (int mf = 0; mf < 4; mf++)                                      \
                ldsm_x4(al[mf][0], al[mf][1], al[mf][2], al[mf][3],             \
                        sA + mf * 16 * SBY + 64);                               \
            _Pragma("unroll")                                                   \
            for (int mf = 0; mf < 4; mf++)                                      \
                _Pragma("unroll")                                               \
                for (int nf = 0; nf < 8; nf++)                                  \
                    mma_bf16(c[mf][nf], al[mf][0], al[mf][1], al[mf][2],        \
                             al[mf][3], bh[nf][0], bh[nf][1]);                  \
        }                                                                       \
        {                                                                       \
            uint32_t bl[8][2];                                                  \
            _Pragma("unroll")                                                   \
            for (int nb = 0; nb < 4; nb++) {                                    \
                uint32_t t0, t1, t2, t3;                                        \
                ldsm_x4(t0, t1, t2, t3, sB + nb * 16 * SBY + 64);               \
                bl[2*nb][0] = t0; bl[2*nb][1] = t1;                             \
                bl[2*nb+1][0] = t2; bl[2*nb+1][1] = t3;                         \
            }                                                                   \
            _Pragma("unroll")                                                   \
            for (int mf = 0; mf < 4; mf++)                                      \
                _Pragma("unroll")                                               \
                for (int nf = 0; nf < 8; nf++)                                  \
                    mma_bf16(c[mf][nf], ah[mf][0], ah[mf][1], ah[mf][2],        \
                             ah[mf][3], bl[nf][0], bl[nf][1]);                  \
        }                                                                       \
    }

// split-K reduction through smem — Round 4 proven
#define KSPLIT_REDUCE()                                                         \
    __syncthreads();                                                            \
    {                                                                           \
        float* red = reinterpret_cast<float*>(sm);                              \
        float* rb = red + (wm * 2 + wn) * 64 * RST;                             \
        if (wk == 1) {                                                          \
            _Pragma("unroll")                                                   \
            for (int mf = 0; mf < 4; mf++)                                      \
                _Pragma("unroll")                                               \
                for (int h = 0; h < 2; h++) {                                   \
                    int row = mf * 16 + tg + 8 * h;                             \
                    float2* rr = reinterpret_cast<float2*>(rb + row * RST);     \
                    _Pragma("unroll")                                           \
                    for (int nf = 0; nf < 8; nf++)                              \
                        rr[nf * 4 + ti] =                                       \
                            make_float2(c[mf][nf][2*h], c[mf][nf][2*h+1]);      \
                }                                                               \
        }                                                                       \
        __syncthreads();                                                        \
        if (wk == 0) {                                                          \
            _Pragma("unroll")                                                   \
            for (int mf = 0; mf < 4; mf++)                                      \
                _Pragma("unroll")                                               \
                for (int h = 0; h < 2; h++) {                                   \
                    int row = mf * 16 + tg + 8 * h;                             \
                    float2* rr = reinterpret_cast<float2*>(rb + row * RST);     \
                    _Pragma("unroll")                                           \
                    for (int nf = 0; nf < 8; nf++) {                            \
                        float2 t = rr[nf * 4 + ti];                             \
                        c[mf][nf][2*h]   += t.x;                                \
                        c[mf][nf][2*h+1] += t.y;                                \
                    }                                                           \
                }                                                               \
        }                                                                       \
    }

// ===========================================================================
// 3) GEMM1: h = silu(x Wg^T) * (x Wu^T)
// ===========================================================================
__global__ __launch_bounds__(256, 1)
void gemm1_tc()
{
    int e = blockIdx.z;
    int cnt = d_count[e];
    int row0 = blockIdx.y * BM;
    if (row0 >= cnt) return;
    int col0 = blockIdx.x * 64;                 // h columns per CTA

    extern __shared__ char sm[];
    __shared__ int toks[BM];
    int tid = threadIdx.x, lane = tid & 31, wid = tid >> 5;

    if (tid < BM) {
        int r = row0 + tid;
        toks[tid] = (r < cnt) ? d_asg[e * T_TOK + r] : -1;
    }
    __syncthreads();

    int lr = tid >> 1, lh = tid & 1;
    int atok = toks[lr];
    bool avalid = (atok >= 0);
    const unsigned char* srcA = avalid ? xbuf + (size_t)(atok >> 1) * NKX * 128 : xbuf;
    int g = lr >> 3, pr = g >> 1, sub = g & 1;
    int o = col0 + pr * 8 + (lr & 7) + (sub ? I_DIM : 0);
    const unsigned char* srcB = w1buf + ((size_t)e * 2816 + o) * NKX * 128;

    int wk = wid >> 2, wm = (wid >> 1) & 1, wn = wid & 1;
    int tg = lane >> 2, ti = lane & 3;
    uint32_t sbase = smem_u32(sm);
    uint32_t aoff = (uint32_t)(wm * 64 + (lane & 15)) * SBY + wk * 32 + (lane >> 4) * 16;
    uint32_t boff = (uint32_t)(wn * 64 + (lane & 7) + ((lane >> 4) & 1) * 8) * SBY
                  + wk * 32 + ((lane >> 3) & 1) * 16;

    float c[4][8][4] = {};
    uint4 av[4], bv[4];
    load_blk(av, srcA, lh, avalid);
    load_blk(bv, srcB, lh, true);

    const int NK = NKX;   // 32
    for (int i = 0; i < NK; i++) {
        int b = i & 1;
        char* A = sm + b * STAGEB;
        store_blk(A + lr * SBY, lh, av);
        store_blk(A + TILEB + lr * SBY, lh, bv);
        __syncthreads();
        if (i + 1 < NK) {
            load_blk(av, srcA + (size_t)(i + 1) * 128, lh, avalid);
            load_blk(bv, srcB + (size_t)(i + 1) * 128, lh, true);
        }
        MMA_SLAB(sbase + b * STAGEB);
    }

    KSPLIT_REDUCE();

    // Epilogue (wk==0): silu(gate)*up -> hbuf hi/lo layout
    if (wk == 0) {
        #pragma unroll
        for (int mf = 0; mf < 4; mf++) {
            #pragma unroll
            for (int h = 0; h < 2; h++) {
                int rloc = wm * 64 + mf * 16 + tg + 8 * h;
                int a = toks[rloc];
                if (a < 0) continue;
                unsigned char* hb = hbuf + (size_t)a * NKH * 128;
                #pragma unroll
                for (int q = 0; q < 4; q++) {
                    float g0 = c[mf][2*q][2*h],   u0 = c[mf][2*q+1][2*h];
                    float g1 = c[mf][2*q][2*h+1], u1 = c[mf][2*q+1][2*h+1];
                    float v0 = u0 * (g0 / (1.f + __expf(-g0)));
                    float v1 = u1 * (g1 / (1.f + __expf(-g1)));
                    int hc = col0 + (wn * 4 + q) * 8 + ti * 2;
                    int s = hc >> 5, cc = hc & 31;
                    unsigned char* bp = hb + (size_t)s * 128 + cc * 2;
                    uint32_t hw, lw;
                    split2(v0, v1, hw, lw);
                    *reinterpret_cast<uint32_t*>(bp)      = hw;
                    *reinterpret_cast<uint32_t*>(bp + 64) = lw;
                }
            }
        }
    }
}

// ===========================================================================
// 4) GEMM2: y = (h down^T) * weight
// ===========================================================================
__global__ __launch_bounds__(256, 1)
void gemm2_tc()
{
    int e = blockIdx.z;
    int cnt = d_count[e];
    int row0 = blockIdx.y * BM;
    if (row0 >= cnt) return;
    int col0 = blockIdx.x * BN;                 // H columns per CTA

    extern __shared__ char sm[];
    __shared__ int toks[BM];
    int tid = threadIdx.x, lane = tid & 31, wid = tid >> 5;

    if (tid < BM) {
        int r = row0 + tid;
        toks[tid] = (r < cnt) ? d_asg[e * T_TOK + r] : -1;
    }
    __syncthreads();

    int lr = tid >> 1, lh = tid & 1;
    int atok = toks[lr];
    bool avalid = (atok >= 0);
    const unsigned char* srcA = avalid ? hbuf + (size_t)atok * NKH * 128 : hbuf;
    const unsigned char* srcB = w2buf + ((size_t)e * 1024 + col0 + lr) * NKH * 128;

    int wk = wid >> 2, wm = (wid >> 1) & 1, wn = wid & 1;
    int tg = lane >> 2, ti = lane & 3;
    uint32_t sbase = smem_u32(sm);
    uint32_t aoff = (uint32_t)(wm * 64 + (lane & 15)) * SBY + wk * 32 + (lane >> 4) * 16;
    uint32_t boff = (uint32_t)(wn * 64 + (lane & 7) + ((lane >> 4) & 1) * 8) * SBY
                  + wk * 32 + ((lane >> 3) & 1) * 16;

    float c[4][8][4] = {};
    uint4 av[4], bv[4];
    load_blk(av, srcA, lh, avalid);
    load_blk(bv, srcB, lh, true);

    const int NK = NKH;   // 44
    for (int i = 0; i < NK; i++) {
        int b = i & 1;
        char* A = sm + b * STAGEB;
        store_blk(A + lr * SBY, lh, av);
        store_blk(A + TILEB + lr * SBY, lh, bv);
        __syncthreads();
        if (i + 1 < NK) {
            load_blk(av, srcA + (size_t)(i + 1) * 128, lh, avalid);
            load_blk(bv, srcB + (size_t)(i + 1) * 128, lh, true);
        }
        MMA_SLAB(sbase + b * STAGEB);
    }

    KSPLIT_REDUCE();

    if (wk == 0) {
        #pragma unroll
        for (int mf = 0; mf < 4; mf++) {
            #pragma unroll
            for (int h = 0; h < 2; h++) {
                int rloc = wm * 64 + mf * 16 + tg + 8 * h;
                int a = toks[rloc];
                if (a < 0) continue;
                float wgt = d_topw[a];
                float* dst = d_yslot + (size_t)a * H_DIM;
                #pragma unroll
                for (int nf = 0; nf < 8; nf++) {
                    int colc = col0 + wn * 64 + nf * 8 + ti * 2;
                    dst[colc]     = c[mf][nf][2*h]   * wgt;
                    dst[colc + 1] = c[mf][nf][2*h+1] * wgt;
                }
            }
        }
    }
}

// ===========================================================================
// 5) Combine
// ===========================================================================
__global__ void combine_kernel(float* __restrict__ out)
{
    int i = blockIdx.x * blockDim.x + threadIdx.x;
    int t = i >> 8;
    int h4 = i & 255;
    const float4* y4 = reinterpret_cast<const float4*>(d_yslot);
    float4 a = y4[(size_t)t * 512 + h4];
    float4 b = y4[(size_t)t * 512 + 256 + h4];
    float4 rr;
    rr.x = a.x + b.x; rr.y = a.y + b.y; rr.z = a.z + b.z; rr.w = a.w + b.w;
    reinterpret_cast<float4*>(out)[i] = rr;
}

// ===========================================================================
extern "C" void kernel_launch(void* const* d_in, const int* in_sizes, int n_in,
                              void* d_out, int out_size)
{
    const float* hidden = (const float*)d_in[0];
    const float* rw     = (const float*)d_in[1];
    const float* gup    = (const float*)d_in[2];
    const float* down   = (const float*)d_in[3];
    float* out          = (float*)d_out;

    cudaFuncSetAttribute(gemm1_tc, cudaFuncAttributeMaxDynamicSharedMemorySize, SMEM_BYTES);
    cudaFuncSetAttribute(gemm2_tc, cudaFuncAttributeMaxDynamicSharedMemorySize, SMEM_BYTES);

    // Pre-convert x, gate_up, down to hi/lo bf16 slab layout (dst chosen in-kernel)
    {
        int tx = T_TOK * NKX * 4;
        conv_hl<<<(tx + 255) / 256, 256>>>(hidden, 0, tx);
        int t1 = E_NUM * 2816 * NKX * 4;
        conv_hl<<<(t1 + 255) / 256, 256>>>(gup, 1, t1);
        int t2 = E_NUM * 1024 * NKH * 4;
        conv_hl<<<(t2 + 255) / 256, 256>>>(down, 2, t2);
    }

    router_kernel<<<T_TOK, 256>>>(hidden, rw);
    build_lists_kernel<<<1, 256>>>();

    {
        dim3 grid(I_DIM / 64, T_TOK / BM, E_NUM);    // 22 x 32 x 8
        gemm1_tc<<<grid, 256, SMEM_BYTES>>>();
    }
    {
        dim3 grid(H_DIM / BN, T_TOK / BM, E_NUM);    // 8 x 32 x 8
        gemm2_tc<<<grid, 256, SMEM_BYTES>>>();
    }
    {
        int n4 = T_TOK * H_DIM / 4;
        combine_kernel<<<n4 / 256, 256>>>(out);
    }
}